// round 8
// baseline (speedup 1.0000x reference)
#include <cuda_runtime.h>

// Problem shape (ParallelScan: B=4, S=4096, D=2048, fp32)
#define BB      4
#define SSEQ    4096
#define DDIM    2048

#define TPB     256          // threads per block (K1/K3)
#define VPT     4            // floats per thread (float4)
#define TW      (TPB*VPT)    // 1024 d-columns per block tile
#define DT      (DDIM/TW)    // 2 d-tiles
#define LCH     64           // rows per chunk -> 512 blocks = single wave
#define NCHUNK  (SSEQ/LCH)   // 64 chunks per chain
#define NCHAIN  (BB*DT)      // 8 chains
#define F4CH    (TW/VPT)     // 256 float4-columns per chain tile (== TPB)

// Scratch: chunk compositions / exclusive prefixes (2 MB each -> L2-resident).
__device__ float g_aggA[NCHAIN*NCHUNK*TW];
__device__ float g_aggB[NCHAIN*NCHUNK*TW];
__device__ int   g_cnt[NCHAIN];   // zero-initialized at load; self-resetting per launch

__device__ __forceinline__ float4 f4_fma(float4 a, float4 h, float4 b) {
    return make_float4(fmaf(a.x,h.x,b.x), fmaf(a.y,h.y,b.y),
                       fmaf(a.z,h.z,b.z), fmaf(a.w,h.w,b.w));
}
__device__ __forceinline__ float4 f4_mul(float4 a, float4 b) {
    return make_float4(a.x*b.x, a.y*b.y, a.z*b.z, a.w*b.w);
}

// ---------------- K1: per-chunk composition + fused per-chain prefix scan --------
// Each block computes its chunk's composition (A,B) and publishes it. The LAST
// block to finish within a chain (fence + atomic counter) then performs that
// chain's serial scan over the 64 chunk aggregates, column-parallel across the
// 256 threads (one float4-column each), rewriting g_aggB in place with the
// EXCLUSIVE prefix (state entering each chunk). Counter self-resets for graph replay.
__global__ __launch_bounds__(TPB)
void k1_aggregate_scan(const float* __restrict__ a,
                       const float* __restrict__ b,
                       const float* __restrict__ h0)
{
    const int chunk = blockIdx.x;
    const int dtile = blockIdx.y;
    const int batch = blockIdx.z;
    const int chain = batch * DT + dtile;
    const int col   = dtile * TW + threadIdx.x * VPT;
    const size_t base = ((size_t)batch * SSEQ + (size_t)chunk * LCH) * DDIM + col;

    float4 A  = make_float4(1.f,1.f,1.f,1.f);
    float4 Bc = make_float4(0.f,0.f,0.f,0.f);

    if (chunk == 0) {
        // fold h0 into the first element: b0' = b0 + a0*h0
        float4 h  = *(const float4*)(h0 + (size_t)batch * DDIM + col);
        float4 a0 = *(const float4*)(a + base);
        float4 b0 = *(const float4*)(b + base);
        Bc = f4_fma(a0, h, b0);
        A  = a0;
#pragma unroll 8
        for (int i = 1; i < LCH; i++) {
            float4 ra = *(const float4*)(a + base + (size_t)i * DDIM);
            float4 rb = *(const float4*)(b + base + (size_t)i * DDIM);
            Bc = f4_fma(ra, Bc, rb);
            A  = f4_mul(A, ra);
        }
    } else {
#pragma unroll 8
        for (int i = 0; i < LCH; i++) {
            float4 ra = *(const float4*)(a + base + (size_t)i * DDIM);
            float4 rb = *(const float4*)(b + base + (size_t)i * DDIM);
            Bc = f4_fma(ra, Bc, rb);
            A  = f4_mul(A, ra);
        }
    }

    const int slot = (chain * NCHUNK + chunk) * TW + threadIdx.x * VPT;
    *(float4*)(g_aggA + slot) = A;
    *(float4*)(g_aggB + slot) = Bc;

    // ---- last-block-per-chain election ----
    __threadfence();          // release: aggregate stores visible before counter bump
    __syncthreads();          // all threads' stores done before thread 0 bumps
    __shared__ int s_last;
    if (threadIdx.x == 0)
        s_last = (atomicAdd(&g_cnt[chain], 1) == NCHUNK - 1);
    __syncthreads();
    if (!s_last) return;

    __threadfence();          // acquire: see all other blocks' aggregates

    // ---- per-chain serial scan (column-parallel), exclusive prefix in place ----
    const int cbase = chain * NCHUNK * TW + threadIdx.x * VPT;
    float4 cB = make_float4(0.f,0.f,0.f,0.f);

    int s = cbase;
    float4 gA = *(const float4*)(g_aggA + s);
    float4 gB = *(const float4*)(g_aggB + s);
#pragma unroll 4
    for (int k = 0; k < NCHUNK; k++) {
        const int s2 = s + TW;
        float4 nA, nB;
        if (k + 1 < NCHUNK) {
            nA = *(const float4*)(g_aggA + s2);   // prefetch next aggregate (L2-hot)
            nB = *(const float4*)(g_aggB + s2);
        }
        *(float4*)(g_aggB + s) = cB;              // exclusive prefix (entry state)
        cB = f4_fma(gA, cB, gB);                  // carry = gA*carry + gB
        gA = nA; gB = nB; s = s2;
    }

    // reset counter for next graph replay (this block is last to touch it)
    if (threadIdx.x == 0) g_cnt[chain] = 0;
}

// ---------------- K3: replay recurrence with entry state, write output ----------
__global__ __launch_bounds__(TPB)
void k3_apply(const float* __restrict__ a,
              const float* __restrict__ b,
              const float* __restrict__ h0,
              float* __restrict__ out)
{
    const int chunk = blockIdx.x;
    const int dtile = blockIdx.y;
    const int batch = blockIdx.z;
    const int chain = batch * DT + dtile;
    const int col   = dtile * TW + threadIdx.x * VPT;
    const size_t base = ((size_t)batch * SSEQ + (size_t)chunk * LCH) * DDIM + col;

    // Entry state. K3 replays from RAW b, so:
    //   chunk 0:    true entry state is h0 (excB there is 0 and b0 is unfolded)
    //   chunk >= 1: excB already equals the true h at chunk entry
    float4 h;
    if (chunk == 0) {
        h = *(const float4*)(h0 + (size_t)batch * DDIM + col);
    } else {
        const int slot = (chain * NCHUNK + chunk) * TW + threadIdx.x * VPT;
        h = *(const float4*)(g_aggB + slot);
    }

#pragma unroll 4
    for (int i = 0; i < LCH; i++) {
        float4 ra = *(const float4*)(a + base + (size_t)i * DDIM);
        float4 rb = *(const float4*)(b + base + (size_t)i * DDIM);
        h = f4_fma(ra, h, rb);
        __stcs((float4*)(out + base + (size_t)i * DDIM), h);   // streaming store
    }
}

extern "C" void kernel_launch(void* const* d_in, const int* in_sizes, int n_in,
                              void* d_out, int out_size)
{
    const float* a  = (const float*)d_in[0];
    const float* b  = (const float*)d_in[1];
    const float* h0 = (const float*)d_in[2];
    float* out = (float*)d_out;

    dim3 g1(NCHUNK, DT, BB);
    k1_aggregate_scan<<<g1, TPB>>>(a, b, h0);

    dim3 g3(NCHUNK, DT, BB);
    k3_apply<<<g3, TPB>>>(a, b, h0, out);
}

// round 9
// speedup vs baseline: 1.0131x; 1.0131x over previous
#include <cuda_runtime.h>

// Problem shape (ParallelScan: B=4, S=4096, D=2048, fp32)
#define BB      4
#define SSEQ    4096
#define DDIM    2048

#define TPB     256          // threads per block
#define VPT     4            // floats per thread (float4)
#define TW      (TPB*VPT)    // 1024 d-columns per block tile
#define DT      (DDIM/TW)    // 2 d-tiles
#define LCH     64           // rows per chunk -> 512 blocks = single wave (all resident)
#define NCHUNK  (SSEQ/LCH)   // 64 chunks per chain
#define NCHAIN  (BB*DT)      // 8 chains
#define GRIDBLKS (NCHUNK*DT*BB)  // 512

// Scratch: chunk compositions / exclusive prefixes (2 MB each -> L2-resident).
__device__ float g_aggA[NCHAIN*NCHUNK*TW];
__device__ float g_aggB[NCHAIN*NCHUNK*TW];

// Grid barrier state. cnt self-resets each use; sense is MONOTONIC across
// barriers and graph replays (each launch consumes 2 sense increments).
__device__ int          g_bar_cnt[2];
__device__ volatile int g_bar_sense;

__device__ __forceinline__ void grid_barrier(int idx, int target) {
    __syncthreads();                      // all my threads' prior work done
    if (threadIdx.x == 0) {
        __threadfence();                  // release my block's global stores
        int prev = atomicAdd(&g_bar_cnt[idx], 1);
        if (prev == GRIDBLKS - 1) {
            g_bar_cnt[idx] = 0;           // reset for next replay
            __threadfence();
            g_bar_sense = target;         // release everyone
        } else {
            while (g_bar_sense < target) __nanosleep(64);
        }
        __threadfence();                  // acquire: see released data
    }
    __syncthreads();
}

__device__ __forceinline__ float4 f4_fma(float4 a, float4 h, float4 b) {
    return make_float4(fmaf(a.x,h.x,b.x), fmaf(a.y,h.y,b.y),
                       fmaf(a.z,h.z,b.z), fmaf(a.w,h.w,b.w));
}
__device__ __forceinline__ float4 f4_mul(float4 a, float4 b) {
    return make_float4(a.x*b.x, a.y*b.y, a.z*b.z, a.w*b.w);
}

// One persistent kernel: phase1 (chunk aggregates) -> barrier -> phase2
// (per-chain prefix scan by the 8 chunk-0 blocks) -> barrier -> phase3 (apply).
__global__ __launch_bounds__(TPB, 4)     // cap regs at 64 -> >=4 blocks/SM -> all 512 resident
void scan_fused(const float* __restrict__ a,
                const float* __restrict__ b,
                const float* __restrict__ h0,
                float* __restrict__ out)
{
    const int chunk = blockIdx.x;
    const int dtile = blockIdx.y;
    const int batch = blockIdx.z;
    const int chain = batch * DT + dtile;
    const int col   = dtile * TW + threadIdx.x * VPT;
    const size_t base = ((size_t)batch * SSEQ + (size_t)chunk * LCH) * DDIM + col;

    // Capture barrier sense base BEFORE any barrier can flip (all blocks are
    // resident and must arrive before a flip, so this read is race-free).
    const int sense0 = g_bar_sense;

    // ================= Phase 1: per-chunk composition (A, B) =================
    float4 A  = make_float4(1.f,1.f,1.f,1.f);
    float4 Bc = make_float4(0.f,0.f,0.f,0.f);

    if (chunk == 0) {
        // fold h0 into the first element: b0' = b0 + a0*h0
        float4 h  = *(const float4*)(h0 + (size_t)batch * DDIM + col);
        float4 a0 = *(const float4*)(a + base);
        float4 b0 = *(const float4*)(b + base);
        Bc = f4_fma(a0, h, b0);
        A  = a0;
#pragma unroll 8
        for (int i = 1; i < LCH; i++) {
            float4 ra = *(const float4*)(a + base + (size_t)i * DDIM);
            float4 rb = *(const float4*)(b + base + (size_t)i * DDIM);
            Bc = f4_fma(ra, Bc, rb);
            A  = f4_mul(A, ra);
        }
    } else {
#pragma unroll 8
        for (int i = 0; i < LCH; i++) {
            float4 ra = *(const float4*)(a + base + (size_t)i * DDIM);
            float4 rb = *(const float4*)(b + base + (size_t)i * DDIM);
            Bc = f4_fma(ra, Bc, rb);
            A  = f4_mul(A, ra);
        }
    }

    const int slot = (chain * NCHUNK + chunk) * TW + threadIdx.x * VPT;
    *(float4*)(g_aggA + slot) = A;
    *(float4*)(g_aggB + slot) = Bc;

    grid_barrier(0, sense0 + 1);

    // ===== Phase 2: per-chain exclusive prefix scan (8 blocks, L2-resident) ===
    if (chunk == 0) {
        const int cbase = chain * NCHUNK * TW + threadIdx.x * VPT;
        float4 cB = make_float4(0.f,0.f,0.f,0.f);

        // depth-4 prefetch ring hides the dependent L2 load latency
        float4 pA[4], pB[4];
#pragma unroll
        for (int j = 0; j < 4; j++) {
            pA[j] = *(const float4*)(g_aggA + cbase + j * TW);
            pB[j] = *(const float4*)(g_aggB + cbase + j * TW);
        }
        int s = cbase;
#pragma unroll 4
        for (int k = 0; k < NCHUNK; k++) {
            float4 gA = pA[k & 3], gB = pB[k & 3];
            if (k + 4 < NCHUNK) {
                pA[k & 3] = *(const float4*)(g_aggA + s + 4 * TW);
                pB[k & 3] = *(const float4*)(g_aggB + s + 4 * TW);
            }
            *(float4*)(g_aggB + s) = cB;          // exclusive prefix (entry state)
            cB = f4_fma(gA, cB, gB);              // carry = gA*carry + gB
            s += TW;
        }
    }

    grid_barrier(1, sense0 + 2);

    // ================= Phase 3: replay recurrence, write output ===============
    // Replays from RAW b, so chunk 0's true entry state is h0 (excB there is 0).
    float4 h;
    if (chunk == 0) {
        h = *(const float4*)(h0 + (size_t)batch * DDIM + col);
    } else {
        h = *(const float4*)(g_aggB + slot);
    }

#pragma unroll 4
    for (int i = 0; i < LCH; i++) {
        float4 ra = *(const float4*)(a + base + (size_t)i * DDIM);
        float4 rb = *(const float4*)(b + base + (size_t)i * DDIM);
        h = f4_fma(ra, h, rb);
        __stcs((float4*)(out + base + (size_t)i * DDIM), h);   // streaming store
    }
}

extern "C" void kernel_launch(void* const* d_in, const int* in_sizes, int n_in,
                              void* d_out, int out_size)
{
    const float* a  = (const float*)d_in[0];
    const float* b  = (const float*)d_in[1];
    const float* h0 = (const float*)d_in[2];
    float* out = (float*)d_out;

    dim3 grid(NCHUNK, DT, BB);
    scan_fused<<<grid, TPB>>>(a, b, h0, out);
}